// round 15
// baseline (speedup 1.0000x reference)
#include <cuda_runtime.h>
#include <cuda_fp16.h>
#include <cstdint>

#define DEV_INLINE __device__ __forceinline__

// ---------------- scratch (device globals; allocation-free) ----------------
__device__ __align__(16) __half g_vt[256u * 4096u];   // V fp16
__device__ __align__(16) __half g_ut[4096u * 256u];   // U fp16
__device__ __align__(16) __half g_t [8192u * 256u];   // T fp16

// ---------------- PTX helpers ----------------
DEV_INLINE uint32_t smem_u32(const void* p) {
    uint32_t a;
    asm("{ .reg .u64 t; cvta.to.shared.u64 t, %1; cvt.u32.u64 %0, t; }"
        : "=r"(a) : "l"(p));
    return a;
}

#define CP_ASYNC16(dst, src) \
    asm volatile("cp.async.cg.shared.global [%0], [%1], 16;" :: "r"(dst), "l"(src))
#define CP_COMMIT() asm volatile("cp.async.commit_group;" ::: "memory")
#define CP_WAIT1()  asm volatile("cp.async.wait_group 1;" ::: "memory")
#define CP_WAIT2()  asm volatile("cp.async.wait_group 2;" ::: "memory")

#define LDSM4(r, addr) \
    asm volatile("ldmatrix.sync.aligned.m8n8.x4.shared.b16 {%0,%1,%2,%3}, [%4];" \
                 : "=r"((r)[0]), "=r"((r)[1]), "=r"((r)[2]), "=r"((r)[3]) \
                 : "r"(addr))

#define MMA_F16(d, a, b) \
    asm volatile("mma.sync.aligned.m16n8k16.row.col.f32.f16.f16.f32 " \
                 "{%0,%1,%2,%3},{%4,%5,%6,%7},{%8,%9},{%0,%1,%2,%3};" \
                 : "+f"((d)[0]), "+f"((d)[1]), "+f"((d)[2]), "+f"((d)[3]) \
                 : "r"((a)[0]), "r"((a)[1]), "r"((a)[2]), "r"((a)[3]), \
                   "r"((b)[0]), "r"((b)[1]))

// ---------------- tiling constants ----------------
// stage 1 (unchanged from best): KT=32, stride 40 halves
static constexpr int KT1 = 32;
static constexpr int STR1 = 40;
static constexpr int NST1 = 4;
static constexpr uint32_t A1_TILE_B = 64u  * STR1 * 2u;  // 5120 B
static constexpr uint32_t B1_TILE_B = 128u * STR1 * 2u;  // 10240 B
static constexpr uint32_t STAGE1_B  = A1_TILE_B + B1_TILE_B;  // 15360 B
static constexpr uint32_t SMEM1_SZ  = NST1 * STAGE1_B;        // 61440 B (occ 2)
// stage 2: KT=64, stride 72 halves (144B rows), NST=3
static constexpr int KT2 = 64;
static constexpr int STR2 = 72;
static constexpr int NST2 = 3;
static constexpr uint32_t A2_TILE_B = 128u * STR2 * 2u;  // 18432 B
static constexpr uint32_t STAGE2_B  = 2u * A2_TILE_B;    // 36864 B
static constexpr uint32_t SMEM2_SZ  = NST2 * STAGE2_B;   // 110592 B (occ 2: 216KB/SM)

// ---------------- convert V and U to fp16 (16 elems/thread, MLP 4) ----------------
__global__ void cvt_vu(const float* __restrict__ V, __half* __restrict__ vt,
                       const float* __restrict__ U, __half* __restrict__ ut, int n1) {
    int i = (blockIdx.x * 256 + threadIdx.x) * 16;
    const float* s; __half* d;
    if (i < n1) { s = V; d = vt; }
    else        { s = U; d = ut; i -= n1; }
    float4 v0 = *reinterpret_cast<const float4*>(&s[i]);
    float4 v1 = *reinterpret_cast<const float4*>(&s[i + 4]);
    float4 v2 = *reinterpret_cast<const float4*>(&s[i + 8]);
    float4 v3 = *reinterpret_cast<const float4*>(&s[i + 12]);
    __half2 p0 = __floats2half2_rn(v0.x, v0.y), p1 = __floats2half2_rn(v0.z, v0.w);
    __half2 p2 = __floats2half2_rn(v1.x, v1.y), p3 = __floats2half2_rn(v1.z, v1.w);
    __half2 p4 = __floats2half2_rn(v2.x, v2.y), p5 = __floats2half2_rn(v2.z, v2.w);
    __half2 p6 = __floats2half2_rn(v3.x, v3.y), p7 = __floats2half2_rn(v3.z, v3.w);
    uint4 o0, o1;
    o0.x = *reinterpret_cast<uint32_t*>(&p0); o0.y = *reinterpret_cast<uint32_t*>(&p1);
    o0.z = *reinterpret_cast<uint32_t*>(&p2); o0.w = *reinterpret_cast<uint32_t*>(&p3);
    o1.x = *reinterpret_cast<uint32_t*>(&p4); o1.y = *reinterpret_cast<uint32_t*>(&p5);
    o1.z = *reinterpret_cast<uint32_t*>(&p6); o1.w = *reinterpret_cast<uint32_t*>(&p7);
    *reinterpret_cast<uint4*>(&d[i])     = o0;
    *reinterpret_cast<uint4*>(&d[i + 8]) = o1;
}

// ---------------- Stage 1: T = x @ V^T (unchanged from R14 best) ----------------
__global__ __launch_bounds__(256, 2)
void lr_gemm_s1(const float* __restrict__ X, const __half* __restrict__ Vt,
                int K, __half* __restrict__ T) {
    extern __shared__ __align__(16) char smem[];
    const uint32_t sb = smem_u32(smem);

    const int tid  = threadIdx.x;
    const int lane = tid & 31;
    const int warp = tid >> 5;
    const int wm = warp & 1, wn = warp >> 1;
    const int m0 = blockIdx.y * 64;
    const int n0 = blockIdx.x * 128;
    const int nk = K / KT1;   // 128

    const int apr = tid >> 2, apk = (tid & 3) * 8;
    const int bpr = tid >> 1, bpb = (tid & 1) * 32;

    const float*  Xb  = X  + (size_t)(m0 + apr) * K + apk;
    const __half* Vb  = Vt + (size_t)(n0 + bpr) * K;
    const uint32_t adst = (uint32_t)(apr * STR1 + apk) * 2;
    const uint32_t bdst = (uint32_t)(bpr * STR1) * 2 + bpb;

    auto produceB = [&](int j) {
        if (j < nk) {
            const uint32_t st = sb + (uint32_t)(j % NST1) * STAGE1_B + A1_TILE_B;
            const __half* src = Vb + (size_t)j * KT1 + bpb / 2;
            CP_ASYNC16(st + bdst,      src);
            CP_ASYNC16(st + bdst + 16, src + 8);
        }
        CP_COMMIT();
    };

    float ra[8];
    auto loadA = [&](int j) {
        if (j < nk) {
            const float* p = Xb + (size_t)j * KT1;
            float4 v0 = *reinterpret_cast<const float4*>(p);
            float4 v1 = *reinterpret_cast<const float4*>(p + 4);
            ra[0] = v0.x; ra[1] = v0.y; ra[2] = v0.z; ra[3] = v0.w;
            ra[4] = v1.x; ra[5] = v1.y; ra[6] = v1.z; ra[7] = v1.w;
        }
    };
    auto stsA = [&](int j) {
        const uint32_t st = (uint32_t)(j % NST1) * STAGE1_B;
        __half2 p0 = __floats2half2_rn(ra[0], ra[1]);
        __half2 p1 = __floats2half2_rn(ra[2], ra[3]);
        __half2 p2 = __floats2half2_rn(ra[4], ra[5]);
        __half2 p3 = __floats2half2_rn(ra[6], ra[7]);
        uint4 v;
        v.x = *reinterpret_cast<uint32_t*>(&p0);
        v.y = *reinterpret_cast<uint32_t*>(&p1);
        v.z = *reinterpret_cast<uint32_t*>(&p2);
        v.w = *reinterpret_cast<uint32_t*>(&p3);
        *reinterpret_cast<uint4*>(smem + st + adst) = v;
    };

    float acc[2][4][4];
#pragma unroll
    for (int mt = 0; mt < 2; mt++)
#pragma unroll
        for (int nt = 0; nt < 4; nt++)
#pragma unroll
            for (int e = 0; e < 4; e++) acc[mt][nt][e] = 0.0f;

    const int lr = lane & 7, lm = lane >> 3;
    const uint32_t offA = (uint32_t)(((lm & 1) * 8 + lr) * STR1 + (lm >> 1) * 8) * 2;
    const uint32_t offB = (uint32_t)(((lm >> 1) * 8 + lr) * STR1 + (lm & 1) * 8) * 2;
    const uint32_t rowA = (uint32_t)(wm * 32) * STR1 * 2;
    const uint32_t rowB = (uint32_t)(wn * 32) * STR1 * 2;

    loadA(0);
    produceB(0);
    produceB(1);
    produceB(2);

    for (int i = 0; i < nk; i++) {
        stsA(i);
        loadA(i + 1);
        CP_WAIT2();
        __syncthreads();
        produceB(i + 3);
        const uint32_t st = sb + (uint32_t)(i % NST1) * STAGE1_B;
        const uint32_t aB = st + rowA + offA;
        const uint32_t bB = st + A1_TILE_B + rowB + offB;
        uint32_t a0[8], b0[8], a1[8], b1[8];
        LDSM4(&a0[0], aB);
        LDSM4(&a0[4], aB + 16u * STR1 * 2);
        LDSM4(&b0[0], bB);
        LDSM4(&b0[4], bB + 16u * STR1 * 2);
        LDSM4(&a1[0], aB + 32);
        LDSM4(&a1[4], aB + 32 + 16u * STR1 * 2);
        LDSM4(&b1[0], bB + 32);
        LDSM4(&b1[4], bB + 32 + 16u * STR1 * 2);
#pragma unroll
        for (int mt = 0; mt < 2; mt++)
#pragma unroll
            for (int nt = 0; nt < 4; nt++)
                MMA_F16(acc[mt][nt], (&a0[mt * 4]), (&b0[nt * 2]));
#pragma unroll
        for (int mt = 0; mt < 2; mt++)
#pragma unroll
            for (int nt = 0; nt < 4; nt++)
                MMA_F16(acc[mt][nt], (&a1[mt * 4]), (&b1[nt * 2]));
    }

    const int er = lane >> 2, ec = (lane & 3) * 2;
#pragma unroll
    for (int nt = 0; nt < 4; nt++) {
        const int col = n0 + wn * 32 + nt * 8 + ec;
#pragma unroll
        for (int mt = 0; mt < 2; mt++) {
            const int r0g = m0 + wm * 32 + mt * 16 + er;
#pragma unroll
            for (int h = 0; h < 2; h++) {
                const int row = r0g + h * 8;
                __half2 o = __floats2half2_rn(acc[mt][nt][h * 2 + 0],
                                              acc[mt][nt][h * 2 + 1]);
                *reinterpret_cast<__half2*>(&T[(size_t)row * 256 + col]) = o;
            }
        }
    }
}

// ---------------- Stage 2: out = T @ U^T + bias ----------------
// BM=128, BN=128, 256 thr, warp tile 64x32. KT=64 (4 turns), NST=3, occ 2.
__global__ __launch_bounds__(256, 2)
void lr_gemm_s2(const __half* __restrict__ At, const __half* __restrict__ Bt,
                int K, int Nout, const float* __restrict__ bias,
                float* __restrict__ Cf) {
    extern __shared__ __align__(16) char smem[];
    const uint32_t sb = smem_u32(smem);

    const int tid  = threadIdx.x;
    const int lane = tid & 31;
    const int warp = tid >> 5;
    const int wm = warp & 1, wn = warp >> 1;
    const int m0 = blockIdx.y * 128;
    const int n0 = blockIdx.x * 128;
    const int nk = K / KT2;    // 4

    // producers: row = tid>>1 (0..127), byte offset (tid&1)*64; 4x16B per operand
    const int pr = tid >> 1, pb = (tid & 1) * 64;
    const __half* Ab = At + (size_t)(m0 + pr) * K + pb / 2;
    const __half* Bb = Bt + (size_t)(n0 + pr) * K + pb / 2;
    const uint32_t pdst = (uint32_t)(pr * STR2) * 2 + pb;

    auto produce = [&](int j) {
        if (j < nk) {
            const uint32_t st = sb + (uint32_t)(j % NST2) * STAGE2_B;
            const __half* as = Ab + (size_t)j * KT2;
            const __half* bs = Bb + (size_t)j * KT2;
#pragma unroll
            for (int q = 0; q < 4; q++) {
                CP_ASYNC16(st + pdst + q * 16,             as + q * 8);
                CP_ASYNC16(st + A2_TILE_B + pdst + q * 16, bs + q * 8);
            }
        }
        CP_COMMIT();
    };

    float acc[4][4][4];
#pragma unroll
    for (int mt = 0; mt < 4; mt++)
#pragma unroll
        for (int nt = 0; nt < 4; nt++)
#pragma unroll
            for (int e = 0; e < 4; e++) acc[mt][nt][e] = 0.0f;

    const int lr = lane & 7, lm = lane >> 3;
    const uint32_t offA = (uint32_t)(((lm & 1) * 8 + lr) * STR2 + (lm >> 1) * 8) * 2;
    const uint32_t offB = (uint32_t)(((lm >> 1) * 8 + lr) * STR2 + (lm & 1) * 8) * 2;
    const uint32_t rowA = (uint32_t)(wm * 64) * STR2 * 2;
    const uint32_t rowB = (uint32_t)(wn * 32) * STR2 * 2;

    produce(0);
    produce(1);

    for (int i = 0; i < nk; i++) {
        CP_WAIT1();
        __syncthreads();
        produce(i + 2);
        const uint32_t st = sb + (uint32_t)(i % NST2) * STAGE2_B;
        const uint32_t aB = st + rowA + offA;
        const uint32_t bB = st + A2_TILE_B + rowB + offB;
#pragma unroll
        for (int ks = 0; ks < 4; ks++) {
            const uint32_t kb = (uint32_t)ks * 16 * 2;    // 16 halves per k16 step
            uint32_t a[4][4], b[8];
#pragma unroll
            for (int mt = 0; mt < 4; mt++)
                LDSM4(a[mt], aB + kb + (uint32_t)mt * 16u * STR2 * 2);
            LDSM4(&b[0], bB + kb);
            LDSM4(&b[4], bB + kb + 16u * STR2 * 2);
#pragma unroll
            for (int mt = 0; mt < 4; mt++)
#pragma unroll
                for (int nt = 0; nt < 4; nt++)
                    MMA_F16(acc[mt][nt], a[mt], (&b[nt * 2]));
        }
    }

    const int er = lane >> 2, ec = (lane & 3) * 2;
#pragma unroll
    for (int nt = 0; nt < 4; nt++) {
        const int col = n0 + wn * 32 + nt * 8 + ec;
        const float b0 = bias[col], b1 = bias[col + 1];
#pragma unroll
        for (int mt = 0; mt < 4; mt++) {
            const int r0g = m0 + wm * 64 + mt * 16 + er;
#pragma unroll
            for (int h = 0; h < 2; h++) {
                const int row = r0g + h * 8;
                float2 o = make_float2(acc[mt][nt][h * 2 + 0] + b0,
                                       acc[mt][nt][h * 2 + 1] + b1);
                *reinterpret_cast<float2*>(&Cf[(size_t)row * Nout + col]) = o;
            }
        }
    }
}

// ---------------- launch ----------------
extern "C" void kernel_launch(void* const* d_in, const int* in_sizes, int n_in,
                              void* d_out, int out_size) {
    const float* x    = (const float*)d_in[0];   // [8192, 4096]
    const float* U    = (const float*)d_in[1];   // [4096, 256]
    const float* V    = (const float*)d_in[2];   // [256, 4096]
    const float* bias = (const float*)d_in[3];   // [4096]
    float* out = (float*)d_out;                  // [8192, 4096]

    __half *vt, *ut, *T;
    cudaGetSymbolAddress((void**)&vt, g_vt);
    cudaGetSymbolAddress((void**)&ut, g_ut);
    cudaGetSymbolAddress((void**)&T,  g_t);

    cudaFuncSetAttribute(lr_gemm_s1, cudaFuncAttributeMaxDynamicSharedMemorySize, SMEM1_SZ);
    cudaFuncSetAttribute(lr_gemm_s2, cudaFuncAttributeMaxDynamicSharedMemorySize, SMEM2_SZ);

    // convert V and U to fp16 (one tiny launch, 16 elems/thread)
    const int n1 = 256 * 4096;
    cvt_vu<<<(2 * n1 / 16) / 256, 256>>>(V, vt, U, ut, n1);

    // Stage 1: T[8192,256] = x @ V^T (K=4096): 256 CTAs, occ 2
    lr_gemm_s1<<<dim3(256 / 128, 8192 / 64), 256, SMEM1_SZ>>>(x, vt, 4096, T);

    // Stage 2: out[8192,4096] = T @ U^T + bias (K=256): 2048 CTAs, occ 2, 4 turns
    lr_gemm_s2<<<dim3(4096 / 128, 8192 / 128), 256, SMEM2_SZ>>>(
        T, ut, 256, 4096, bias, out);
}

// round 16
// speedup vs baseline: 1.0512x; 1.0512x over previous
#include <cuda_runtime.h>
#include <cuda_fp16.h>
#include <cstdint>

#define DEV_INLINE __device__ __forceinline__

// ---------------- scratch (device globals; allocation-free) ----------------
__device__ __align__(16) __half g_vt[256u * 4096u];   // V fp16
__device__ __align__(16) __half g_ut[4096u * 256u];   // U fp16
__device__ __align__(16) __half g_t [8192u * 256u];   // T fp16

// ---------------- PTX helpers ----------------
DEV_INLINE uint32_t smem_u32(const void* p) {
    uint32_t a;
    asm("{ .reg .u64 t; cvta.to.shared.u64 t, %1; cvt.u32.u64 %0, t; }"
        : "=r"(a) : "l"(p));
    return a;
}

#define CP_ASYNC16(dst, src) \
    asm volatile("cp.async.cg.shared.global [%0], [%1], 16;" :: "r"(dst), "l"(src))
#define CP_COMMIT() asm volatile("cp.async.commit_group;" ::: "memory")
#define CP_WAIT2()  asm volatile("cp.async.wait_group 2;" ::: "memory")

#define LDSM4(r, addr) \
    asm volatile("ldmatrix.sync.aligned.m8n8.x4.shared.b16 {%0,%1,%2,%3}, [%4];" \
                 : "=r"((r)[0]), "=r"((r)[1]), "=r"((r)[2]), "=r"((r)[3]) \
                 : "r"(addr))

#define MMA_F16(d, a, b) \
    asm volatile("mma.sync.aligned.m16n8k16.row.col.f32.f16.f16.f32 " \
                 "{%0,%1,%2,%3},{%4,%5,%6,%7},{%8,%9},{%0,%1,%2,%3};" \
                 : "+f"((d)[0]), "+f"((d)[1]), "+f"((d)[2]), "+f"((d)[3]) \
                 : "r"((a)[0]), "r"((a)[1]), "r"((a)[2]), "r"((a)[3]), \
                   "r"((b)[0]), "r"((b)[1]))

// ---------------- tiling constants ----------------
static constexpr int KT = 32;                          // halves per K-chunk
static constexpr int STRIDE = 40;                      // halves per smem row (pad)
// stage 1: BM=64, BN=128, NST=4 (R14 best, unchanged)
static constexpr int NST1 = 4;
static constexpr uint32_t A1_TILE_B = 64u  * STRIDE * 2u;  // 5120 B
static constexpr uint32_t B1_TILE_B = 128u * STRIDE * 2u;  // 10240 B
static constexpr uint32_t STAGE1_B  = A1_TILE_B + B1_TILE_B;  // 15360 B
static constexpr uint32_t SMEM1_SZ  = NST1 * STAGE1_B;        // 61440 B (occ 2)
// stage 2: BM=128, BN=128, NST=4, 512 threads (warp 4x4, tile 32x32)
static constexpr int NST2 = 4;
static constexpr uint32_t A2_TILE_B = 128u * STRIDE * 2u;  // 10240 B
static constexpr uint32_t STAGE2_B  = 2u * A2_TILE_B;      // 20480 B
static constexpr uint32_t SMEM2_SZ  = NST2 * STAGE2_B;     // 81920 B (occ 2)

// ---------------- convert V and U to fp16 (R14 version) ----------------
__global__ void cvt_vu(const float* __restrict__ V, __half* __restrict__ vt,
                       const float* __restrict__ U, __half* __restrict__ ut, int n1) {
    int i = (blockIdx.x * 256 + threadIdx.x) * 4;
    const float* s; __half* d;
    if (i < n1) { s = V; d = vt; }
    else        { s = U; d = ut; i -= n1; }
    float4 v = *reinterpret_cast<const float4*>(&s[i]);
    __half2 p0 = __floats2half2_rn(v.x, v.y);
    __half2 p1 = __floats2half2_rn(v.z, v.w);
    *reinterpret_cast<__half2*>(&d[i])     = p0;
    *reinterpret_cast<__half2*>(&d[i + 2]) = p1;
}

// ---------------- Stage 1: T = x @ V^T (unchanged from R14 best) ----------------
__global__ __launch_bounds__(256, 2)
void lr_gemm_s1(const float* __restrict__ X, const __half* __restrict__ Vt,
                int K, __half* __restrict__ T) {
    extern __shared__ __align__(16) char smem[];
    const uint32_t sb = smem_u32(smem);

    const int tid  = threadIdx.x;
    const int lane = tid & 31;
    const int warp = tid >> 5;
    const int wm = warp & 1, wn = warp >> 1;
    const int m0 = blockIdx.y * 64;
    const int n0 = blockIdx.x * 128;
    const int nk = K / KT;   // 128

    const int apr = tid >> 2, apk = (tid & 3) * 8;
    const int bpr = tid >> 1, bpb = (tid & 1) * 32;

    const float*  Xb  = X  + (size_t)(m0 + apr) * K + apk;
    const __half* Vb  = Vt + (size_t)(n0 + bpr) * K;
    const uint32_t adst = (uint32_t)(apr * STRIDE + apk) * 2;
    const uint32_t bdst = (uint32_t)(bpr * STRIDE) * 2 + bpb;

    auto produceB = [&](int j) {
        if (j < nk) {
            const uint32_t st = sb + (uint32_t)(j % NST1) * STAGE1_B + A1_TILE_B;
            const __half* src = Vb + (size_t)j * KT + bpb / 2;
            CP_ASYNC16(st + bdst,      src);
            CP_ASYNC16(st + bdst + 16, src + 8);
        }
        CP_COMMIT();
    };

    float ra[8];
    auto loadA = [&](int j) {
        if (j < nk) {
            const float* p = Xb + (size_t)j * KT;
            float4 v0 = *reinterpret_cast<const float4*>(p);
            float4 v1 = *reinterpret_cast<const float4*>(p + 4);
            ra[0] = v0.x; ra[1] = v0.y; ra[2] = v0.z; ra[3] = v0.w;
            ra[4] = v1.x; ra[5] = v1.y; ra[6] = v1.z; ra[7] = v1.w;
        }
    };
    auto stsA = [&](int j) {
        const uint32_t st = (uint32_t)(j % NST1) * STAGE1_B;
        __half2 p0 = __floats2half2_rn(ra[0], ra[1]);
        __half2 p1 = __floats2half2_rn(ra[2], ra[3]);
        __half2 p2 = __floats2half2_rn(ra[4], ra[5]);
        __half2 p3 = __floats2half2_rn(ra[6], ra[7]);
        uint4 v;
        v.x = *reinterpret_cast<uint32_t*>(&p0);
        v.y = *reinterpret_cast<uint32_t*>(&p1);
        v.z = *reinterpret_cast<uint32_t*>(&p2);
        v.w = *reinterpret_cast<uint32_t*>(&p3);
        *reinterpret_cast<uint4*>(smem + st + adst) = v;
    };

    float acc[2][4][4];
#pragma unroll
    for (int mt = 0; mt < 2; mt++)
#pragma unroll
        for (int nt = 0; nt < 4; nt++)
#pragma unroll
            for (int e = 0; e < 4; e++) acc[mt][nt][e] = 0.0f;

    const int lr = lane & 7, lm = lane >> 3;
    const uint32_t offA = (uint32_t)(((lm & 1) * 8 + lr) * STRIDE + (lm >> 1) * 8) * 2;
    const uint32_t offB = (uint32_t)(((lm >> 1) * 8 + lr) * STRIDE + (lm & 1) * 8) * 2;
    const uint32_t rowA = (uint32_t)(wm * 32) * STRIDE * 2;
    const uint32_t rowB = (uint32_t)(wn * 32) * STRIDE * 2;

    loadA(0);
    produceB(0);
    produceB(1);
    produceB(2);

    for (int i = 0; i < nk; i++) {
        stsA(i);
        loadA(i + 1);
        CP_WAIT2();
        __syncthreads();
        produceB(i + 3);
        const uint32_t st = sb + (uint32_t)(i % NST1) * STAGE1_B;
        const uint32_t aB = st + rowA + offA;
        const uint32_t bB = st + A1_TILE_B + rowB + offB;
        uint32_t a0[8], b0[8], a1[8], b1[8];
        LDSM4(&a0[0], aB);
        LDSM4(&a0[4], aB + 16u * STRIDE * 2);
        LDSM4(&b0[0], bB);
        LDSM4(&b0[4], bB + 16u * STRIDE * 2);
        LDSM4(&a1[0], aB + 32);
        LDSM4(&a1[4], aB + 32 + 16u * STRIDE * 2);
        LDSM4(&b1[0], bB + 32);
        LDSM4(&b1[4], bB + 32 + 16u * STRIDE * 2);
#pragma unroll
        for (int mt = 0; mt < 2; mt++)
#pragma unroll
            for (int nt = 0; nt < 4; nt++)
                MMA_F16(acc[mt][nt], (&a0[mt * 4]), (&b0[nt * 2]));
#pragma unroll
        for (int mt = 0; mt < 2; mt++)
#pragma unroll
            for (int nt = 0; nt < 4; nt++)
                MMA_F16(acc[mt][nt], (&a1[mt * 4]), (&b1[nt * 2]));
    }

    const int er = lane >> 2, ec = (lane & 3) * 2;
#pragma unroll
    for (int nt = 0; nt < 4; nt++) {
        const int col = n0 + wn * 32 + nt * 8 + ec;
#pragma unroll
        for (int mt = 0; mt < 2; mt++) {
            const int r0g = m0 + wm * 32 + mt * 16 + er;
#pragma unroll
            for (int h = 0; h < 2; h++) {
                const int row = r0g + h * 8;
                __half2 o = __floats2half2_rn(acc[mt][nt][h * 2 + 0],
                                              acc[mt][nt][h * 2 + 1]);
                *reinterpret_cast<__half2*>(&T[(size_t)row * 256 + col]) = o;
            }
        }
    }
}

// ---------------- Stage 2: out = T @ U^T + bias ----------------
// BM=128, BN=128, 512 thr, warp grid 4x4 (tile 32x32). KT=32, NST=4, occ 2.
__global__ __launch_bounds__(512, 2)
void lr_gemm_s2(const __half* __restrict__ At, const __half* __restrict__ Bt,
                int K, int Nout, const float* __restrict__ bias,
                float* __restrict__ Cf) {
    extern __shared__ __align__(16) char smem[];
    const uint32_t sb = smem_u32(smem);

    const int tid  = threadIdx.x;
    const int lane = tid & 31;
    const int warp = tid >> 5;          // 0..15
    const int wm = warp & 3, wn = warp >> 2;
    const int m0 = blockIdx.y * 128;
    const int n0 = blockIdx.x * 128;
    const int nk = K / KT;    // 8

    // producers: 512 thr; row = tid>>2 (0..127), byte offset (tid&3)*16; 1 chunk/operand
    const int pr = tid >> 2, pb = (tid & 3) * 16;
    const __half* Ab = At + (size_t)(m0 + pr) * K + pb / 2;
    const __half* Bb = Bt + (size_t)(n0 + pr) * K + pb / 2;
    const uint32_t pdst = (uint32_t)(pr * STRIDE) * 2 + pb;

    auto produce = [&](int j) {
        if (j < nk) {
            const uint32_t st = sb + (uint32_t)(j % NST2) * STAGE2_B;
            CP_ASYNC16(st + pdst,             Ab + (size_t)j * KT);
            CP_ASYNC16(st + A2_TILE_B + pdst, Bb + (size_t)j * KT);
        }
        CP_COMMIT();
    };

    float acc[2][4][4];
#pragma unroll
    for (int mt = 0; mt < 2; mt++)
#pragma unroll
        for (int nt = 0; nt < 4; nt++)
#pragma unroll
            for (int e = 0; e < 4; e++) acc[mt][nt][e] = 0.0f;

    const int lr = lane & 7, lm = lane >> 3;
    const uint32_t offA = (uint32_t)(((lm & 1) * 8 + lr) * STRIDE + (lm >> 1) * 8) * 2;
    const uint32_t offB = (uint32_t)(((lm >> 1) * 8 + lr) * STRIDE + (lm & 1) * 8) * 2;
    const uint32_t rowA = (uint32_t)(wm * 32) * STRIDE * 2;
    const uint32_t rowB = (uint32_t)(wn * 32) * STRIDE * 2;

    produce(0);
    produce(1);
    produce(2);

    for (int i = 0; i < nk; i++) {
        CP_WAIT2();
        __syncthreads();
        produce(i + 3);
        const uint32_t st = sb + (uint32_t)(i % NST2) * STAGE2_B;
        const uint32_t aB = st + rowA + offA;
        const uint32_t bB = st + A2_TILE_B + rowB + offB;
        uint32_t a0[8], b0[8], a1[8], b1[8];
        LDSM4(&a0[0], aB);
        LDSM4(&a0[4], aB + 16u * STRIDE * 2);
        LDSM4(&b0[0], bB);
        LDSM4(&b0[4], bB + 16u * STRIDE * 2);
        LDSM4(&a1[0], aB + 32);
        LDSM4(&a1[4], aB + 32 + 16u * STRIDE * 2);
        LDSM4(&b1[0], bB + 32);
        LDSM4(&b1[4], bB + 32 + 16u * STRIDE * 2);
#pragma unroll
        for (int mt = 0; mt < 2; mt++)
#pragma unroll
            for (int nt = 0; nt < 4; nt++)
                MMA_F16(acc[mt][nt], (&a0[mt * 4]), (&b0[nt * 2]));
#pragma unroll
        for (int mt = 0; mt < 2; mt++)
#pragma unroll
            for (int nt = 0; nt < 4; nt++)
                MMA_F16(acc[mt][nt], (&a1[mt * 4]), (&b1[nt * 2]));
    }

    const int er = lane >> 2, ec = (lane & 3) * 2;
#pragma unroll
    for (int nt = 0; nt < 4; nt++) {
        const int col = n0 + wn * 32 + nt * 8 + ec;
        const float b0 = bias[col], b1 = bias[col + 1];
#pragma unroll
        for (int mt = 0; mt < 2; mt++) {
            const int r0g = m0 + wm * 32 + mt * 16 + er;
#pragma unroll
            for (int h = 0; h < 2; h++) {
                const int row = r0g + h * 8;
                float2 o = make_float2(acc[mt][nt][h * 2 + 0] + b0,
                                       acc[mt][nt][h * 2 + 1] + b1);
                *reinterpret_cast<float2*>(&Cf[(size_t)row * Nout + col]) = o;
            }
        }
    }
}

// ---------------- launch ----------------
extern "C" void kernel_launch(void* const* d_in, const int* in_sizes, int n_in,
                              void* d_out, int out_size) {
    const float* x    = (const float*)d_in[0];   // [8192, 4096]
    const float* U    = (const float*)d_in[1];   // [4096, 256]
    const float* V    = (const float*)d_in[2];   // [256, 4096]
    const float* bias = (const float*)d_in[3];   // [4096]
    float* out = (float*)d_out;                  // [8192, 4096]

    __half *vt, *ut, *T;
    cudaGetSymbolAddress((void**)&vt, g_vt);
    cudaGetSymbolAddress((void**)&ut, g_ut);
    cudaGetSymbolAddress((void**)&T,  g_t);

    cudaFuncSetAttribute(lr_gemm_s1, cudaFuncAttributeMaxDynamicSharedMemorySize, SMEM1_SZ);
    cudaFuncSetAttribute(lr_gemm_s2, cudaFuncAttributeMaxDynamicSharedMemorySize, SMEM2_SZ);

    // convert V and U to fp16 (one tiny launch)
    const int n1 = 256 * 4096;
    cvt_vu<<<(2 * n1 / 4) / 256, 256>>>(V, vt, U, ut, n1);

    // Stage 1: T[8192,256] = x @ V^T (K=4096): 256 CTAs, occ 2
    lr_gemm_s1<<<dim3(256 / 128, 8192 / 64), 256, SMEM1_SZ>>>(x, vt, 4096, T);

    // Stage 2: out[8192,4096] = T @ U^T + bias (K=256): 2048 CTAs, 512 thr, occ 2
    lr_gemm_s2<<<dim3(4096 / 128, 8192 / 128), 512, SMEM2_SZ>>>(
        T, ut, 256, 4096, bias, out);
}

// round 17
// speedup vs baseline: 1.0651x; 1.0132x over previous
#include <cuda_runtime.h>
#include <cuda_fp16.h>
#include <cstdint>

#define DEV_INLINE __device__ __forceinline__

// ---------------- scratch (device globals; allocation-free) ----------------
__device__ __align__(16) __half g_vt[256u * 4096u];   // V fp16
__device__ __align__(16) __half g_ut[4096u * 256u];   // U fp16
__device__ __align__(16) __half g_t [8192u * 256u];   // T fp16

// ---------------- PTX helpers ----------------
DEV_INLINE uint32_t smem_u32(const void* p) {
    uint32_t a;
    asm("{ .reg .u64 t; cvta.to.shared.u64 t, %1; cvt.u32.u64 %0, t; }"
        : "=r"(a) : "l"(p));
    return a;
}

#define CP_ASYNC16(dst, src) \
    asm volatile("cp.async.cg.shared.global [%0], [%1], 16;" :: "r"(dst), "l"(src))
#define CP_COMMIT() asm volatile("cp.async.commit_group;" ::: "memory")
#define CP_WAIT2()  asm volatile("cp.async.wait_group 2;" ::: "memory")

#define LDSM4(r, addr) \
    asm volatile("ldmatrix.sync.aligned.m8n8.x4.shared.b16 {%0,%1,%2,%3}, [%4];" \
                 : "=r"((r)[0]), "=r"((r)[1]), "=r"((r)[2]), "=r"((r)[3]) \
                 : "r"(addr))

#define MMA_F16(d, a, b) \
    asm volatile("mma.sync.aligned.m16n8k16.row.col.f32.f16.f16.f32 " \
                 "{%0,%1,%2,%3},{%4,%5,%6,%7},{%8,%9},{%0,%1,%2,%3};" \
                 : "+f"((d)[0]), "+f"((d)[1]), "+f"((d)[2]), "+f"((d)[3]) \
                 : "r"((a)[0]), "r"((a)[1]), "r"((a)[2]), "r"((a)[3]), \
                   "r"((b)[0]), "r"((b)[1]))

// ---------------- tiling constants ----------------
static constexpr int KT = 32;                          // halves per K-chunk
static constexpr int STRIDE = 40;                      // halves per smem row (pad)
// stage 1: BM=64, BN=128, NST=4 (R14 best)
static constexpr int NST1 = 4;
static constexpr uint32_t A1_TILE_B = 64u  * STRIDE * 2u;  // 5120 B
static constexpr uint32_t B1_TILE_B = 128u * STRIDE * 2u;  // 10240 B
static constexpr uint32_t STAGE1_B  = A1_TILE_B + B1_TILE_B;  // 15360 B
static constexpr uint32_t SMEM1_SZ  = NST1 * STAGE1_B;        // 61440 B (occ 2)
// stage 2: BM=128, BN=128, NST=4, 256 threads (R14 best)
static constexpr int NST2 = 4;
static constexpr uint32_t A2_TILE_B = 128u * STRIDE * 2u;  // 10240 B
static constexpr uint32_t STAGE2_B  = 2u * A2_TILE_B;      // 20480 B
static constexpr uint32_t SMEM2_SZ  = NST2 * STAGE2_B;     // 81920 B (occ 2)

// ---------------- convert V to fp16 (U handled inside s1's spare CTAs) ----------------
__global__ void cvt_v(const float* __restrict__ V, __half* __restrict__ vt) {
    int i = (blockIdx.x * 256 + threadIdx.x) * 4;
    float4 v = *reinterpret_cast<const float4*>(&V[i]);
    __half2 p0 = __floats2half2_rn(v.x, v.y);
    __half2 p1 = __floats2half2_rn(v.z, v.w);
    *reinterpret_cast<__half2*>(&vt[i])     = p0;
    *reinterpret_cast<__half2*>(&vt[i + 2]) = p1;
}

// ---------------- Stage 1: T = x @ V^T (GEMM path identical to R14 best) ----------------
// grid = dim3(2, 136): y<128 -> GEMM m-bands; y>=128 -> 16 converter CTAs for U.
__global__ __launch_bounds__(256, 2)
void lr_gemm_s1(const float* __restrict__ X, const __half* __restrict__ Vt,
                int K, __half* __restrict__ T,
                const float* __restrict__ U, __half* __restrict__ ut) {
    const int tid = threadIdx.x;

    if (blockIdx.y >= 128) {
        // ---- U converter CTAs: fully overlapped with the GEMM wave ----
        // 16 CTAs x 256 thr = 4096 lanes; 1M elems; 64 coalesced float4 rounds.
        const int c = ((blockIdx.y - 128) * 2 + blockIdx.x) * 256 + tid;
#pragma unroll 4
        for (int q = 0; q < 64; q++) {
            const int i = (q * 4096 + c) * 4;
            float4 v = *reinterpret_cast<const float4*>(&U[i]);
            __half2 p0 = __floats2half2_rn(v.x, v.y);
            __half2 p1 = __floats2half2_rn(v.z, v.w);
            *reinterpret_cast<__half2*>(&ut[i])     = p0;
            *reinterpret_cast<__half2*>(&ut[i + 2]) = p1;
        }
        return;
    }

    extern __shared__ __align__(16) char smem[];
    const uint32_t sb = smem_u32(smem);

    const int lane = tid & 31;
    const int warp = tid >> 5;
    const int wm = warp & 1, wn = warp >> 1;
    const int m0 = blockIdx.y * 64;
    const int n0 = blockIdx.x * 128;
    const int nk = K / KT;   // 128

    const int apr = tid >> 2, apk = (tid & 3) * 8;
    const int bpr = tid >> 1, bpb = (tid & 1) * 32;

    const float*  Xb  = X  + (size_t)(m0 + apr) * K + apk;
    const __half* Vb  = Vt + (size_t)(n0 + bpr) * K;
    const uint32_t adst = (uint32_t)(apr * STRIDE + apk) * 2;
    const uint32_t bdst = (uint32_t)(bpr * STRIDE) * 2 + bpb;

    auto produceB = [&](int j) {
        if (j < nk) {
            const uint32_t st = sb + (uint32_t)(j % NST1) * STAGE1_B + A1_TILE_B;
            const __half* src = Vb + (size_t)j * KT + bpb / 2;
            CP_ASYNC16(st + bdst,      src);
            CP_ASYNC16(st + bdst + 16, src + 8);
        }
        CP_COMMIT();
    };

    float ra[8];
    auto loadA = [&](int j) {
        if (j < nk) {
            const float* p = Xb + (size_t)j * KT;
            float4 v0 = *reinterpret_cast<const float4*>(p);
            float4 v1 = *reinterpret_cast<const float4*>(p + 4);
            ra[0] = v0.x; ra[1] = v0.y; ra[2] = v0.z; ra[3] = v0.w;
            ra[4] = v1.x; ra[5] = v1.y; ra[6] = v1.z; ra[7] = v1.w;
        }
    };
    auto stsA = [&](int j) {
        const uint32_t st = (uint32_t)(j % NST1) * STAGE1_B;
        __half2 p0 = __floats2half2_rn(ra[0], ra[1]);
        __half2 p1 = __floats2half2_rn(ra[2], ra[3]);
        __half2 p2 = __floats2half2_rn(ra[4], ra[5]);
        __half2 p3 = __floats2half2_rn(ra[6], ra[7]);
        uint4 v;
        v.x = *reinterpret_cast<uint32_t*>(&p0);
        v.y = *reinterpret_cast<uint32_t*>(&p1);
        v.z = *reinterpret_cast<uint32_t*>(&p2);
        v.w = *reinterpret_cast<uint32_t*>(&p3);
        *reinterpret_cast<uint4*>(smem + st + adst) = v;
    };

    float acc[2][4][4];
#pragma unroll
    for (int mt = 0; mt < 2; mt++)
#pragma unroll
        for (int nt = 0; nt < 4; nt++)
#pragma unroll
            for (int e = 0; e < 4; e++) acc[mt][nt][e] = 0.0f;

    const int lr = lane & 7, lm = lane >> 3;
    const uint32_t offA = (uint32_t)(((lm & 1) * 8 + lr) * STRIDE + (lm >> 1) * 8) * 2;
    const uint32_t offB = (uint32_t)(((lm >> 1) * 8 + lr) * STRIDE + (lm & 1) * 8) * 2;
    const uint32_t rowA = (uint32_t)(wm * 32) * STRIDE * 2;
    const uint32_t rowB = (uint32_t)(wn * 32) * STRIDE * 2;

    loadA(0);
    produceB(0);
    produceB(1);
    produceB(2);

    for (int i = 0; i < nk; i++) {
        stsA(i);
        loadA(i + 1);
        CP_WAIT2();
        __syncthreads();
        produceB(i + 3);
        const uint32_t st = sb + (uint32_t)(i % NST1) * STAGE1_B;
        const uint32_t aB = st + rowA + offA;
        const uint32_t bB = st + A1_TILE_B + rowB + offB;
        uint32_t a0[8], b0[8], a1[8], b1[8];
        LDSM4(&a0[0], aB);
        LDSM4(&a0[4], aB + 16u * STRIDE * 2);
        LDSM4(&b0[0], bB);
        LDSM4(&b0[4], bB + 16u * STRIDE * 2);
        LDSM4(&a1[0], aB + 32);
        LDSM4(&a1[4], aB + 32 + 16u * STRIDE * 2);
        LDSM4(&b1[0], bB + 32);
        LDSM4(&b1[4], bB + 32 + 16u * STRIDE * 2);
#pragma unroll
        for (int mt = 0; mt < 2; mt++)
#pragma unroll
            for (int nt = 0; nt < 4; nt++)
                MMA_F16(acc[mt][nt], (&a0[mt * 4]), (&b0[nt * 2]));
#pragma unroll
        for (int mt = 0; mt < 2; mt++)
#pragma unroll
            for (int nt = 0; nt < 4; nt++)
                MMA_F16(acc[mt][nt], (&a1[mt * 4]), (&b1[nt * 2]));
    }

    const int er = lane >> 2, ec = (lane & 3) * 2;
#pragma unroll
    for (int nt = 0; nt < 4; nt++) {
        const int col = n0 + wn * 32 + nt * 8 + ec;
#pragma unroll
        for (int mt = 0; mt < 2; mt++) {
            const int r0g = m0 + wm * 32 + mt * 16 + er;
#pragma unroll
            for (int h = 0; h < 2; h++) {
                const int row = r0g + h * 8;
                __half2 o = __floats2half2_rn(acc[mt][nt][h * 2 + 0],
                                              acc[mt][nt][h * 2 + 1]);
                *reinterpret_cast<__half2*>(&T[(size_t)row * 256 + col]) = o;
            }
        }
    }
}

// ---------------- Stage 2: out = T @ U^T + bias (identical to R14 best) ----------------
// BM=128, BN=128, 256 thr, warp tile 64x32 (2 wm x 4 wn, mt=4). NST=4, occ 2.
__global__ __launch_bounds__(256, 2)
void lr_gemm_s2(const __half* __restrict__ At, const __half* __restrict__ Bt,
                int K, int Nout, const float* __restrict__ bias,
                float* __restrict__ Cf) {
    extern __shared__ __align__(16) char smem[];
    const uint32_t sb = smem_u32(smem);

    const int tid  = threadIdx.x;
    const int lane = tid & 31;
    const int warp = tid >> 5;
    const int wm = warp & 1, wn = warp >> 1;
    const int m0 = blockIdx.y * 128;
    const int n0 = blockIdx.x * 128;
    const int nk = K / KT;    // 8

    const int pr = tid >> 1, pb = (tid & 1) * 32;
    const __half* Ab = At + (size_t)(m0 + pr) * K + pb / 2;
    const __half* Bb = Bt + (size_t)(n0 + pr) * K + pb / 2;
    const uint32_t pdst = (uint32_t)(pr * STRIDE) * 2 + pb;

    auto produce = [&](int j) {
        if (j < nk) {
            const uint32_t st = sb + (uint32_t)(j % NST2) * STAGE2_B;
            const __half* as = Ab + (size_t)j * KT;
            const __half* bs = Bb + (size_t)j * KT;
            CP_ASYNC16(st + pdst,      as);
            CP_ASYNC16(st + pdst + 16, as + 8);
            CP_ASYNC16(st + A2_TILE_B + pdst,      bs);
            CP_ASYNC16(st + A2_TILE_B + pdst + 16, bs + 8);
        }
        CP_COMMIT();
    };

    float acc[4][4][4];
#pragma unroll
    for (int mt = 0; mt < 4; mt++)
#pragma unroll
        for (int nt = 0; nt < 4; nt++)
#pragma unroll
            for (int e = 0; e < 4; e++) acc[mt][nt][e] = 0.0f;

    const int lr = lane & 7, lm = lane >> 3;
    const uint32_t offA = (uint32_t)(((lm & 1) * 8 + lr) * STRIDE + (lm >> 1) * 8) * 2;
    const uint32_t offB = (uint32_t)(((lm >> 1) * 8 + lr) * STRIDE + (lm & 1) * 8) * 2;
    const uint32_t rowA = (uint32_t)(wm * 64) * STRIDE * 2;
    const uint32_t rowB = (uint32_t)(wn * 32) * STRIDE * 2;

    produce(0);
    produce(1);
    produce(2);

    for (int i = 0; i < nk; i++) {
        CP_WAIT2();
        __syncthreads();
        produce(i + 3);
        const uint32_t st = sb + (uint32_t)(i % NST2) * STAGE2_B;
        const uint32_t aB = st + rowA + offA;
        const uint32_t bB = st + A2_TILE_B + rowB + offB;
#pragma unroll
        for (int ks = 0; ks < 2; ks++) {
            const uint32_t kb = (uint32_t)ks * 16 * 2;
            uint32_t a[4][4], b[8];
#pragma unroll
            for (int mt = 0; mt < 4; mt++)
                LDSM4(a[mt], aB + kb + (uint32_t)mt * 16u * STRIDE * 2);
            LDSM4(&b[0], bB + kb);
            LDSM4(&b[4], bB + kb + 16u * STRIDE * 2);
#pragma unroll
            for (int mt = 0; mt < 4; mt++)
#pragma unroll
                for (int nt = 0; nt < 4; nt++)
                    MMA_F16(acc[mt][nt], a[mt], (&b[nt * 2]));
        }
    }

    const int er = lane >> 2, ec = (lane & 3) * 2;
#pragma unroll
    for (int nt = 0; nt < 4; nt++) {
        const int col = n0 + wn * 32 + nt * 8 + ec;
        const float b0 = bias[col], b1 = bias[col + 1];
#pragma unroll
        for (int mt = 0; mt < 4; mt++) {
            const int r0g = m0 + wm * 64 + mt * 16 + er;
#pragma unroll
            for (int h = 0; h < 2; h++) {
                const int row = r0g + h * 8;
                float2 o = make_float2(acc[mt][nt][h * 2 + 0] + b0,
                                       acc[mt][nt][h * 2 + 1] + b1);
                *reinterpret_cast<float2*>(&Cf[(size_t)row * Nout + col]) = o;
            }
        }
    }
}

// ---------------- launch ----------------
extern "C" void kernel_launch(void* const* d_in, const int* in_sizes, int n_in,
                              void* d_out, int out_size) {
    const float* x    = (const float*)d_in[0];   // [8192, 4096]
    const float* U    = (const float*)d_in[1];   // [4096, 256]
    const float* V    = (const float*)d_in[2];   // [256, 4096]
    const float* bias = (const float*)d_in[3];   // [4096]
    float* out = (float*)d_out;                  // [8192, 4096]

    __half *vt, *ut, *T;
    cudaGetSymbolAddress((void**)&vt, g_vt);
    cudaGetSymbolAddress((void**)&ut, g_ut);
    cudaGetSymbolAddress((void**)&T,  g_t);

    cudaFuncSetAttribute(lr_gemm_s1, cudaFuncAttributeMaxDynamicSharedMemorySize, SMEM1_SZ);
    cudaFuncSetAttribute(lr_gemm_s2, cudaFuncAttributeMaxDynamicSharedMemorySize, SMEM2_SZ);

    // convert V only (U conversion rides inside s1's spare CTAs)
    cvt_v<<<(256 * 4096 / 4) / 256, 256>>>(V, vt);

    // Stage 1: T = x @ V^T (256 GEMM CTAs + 16 U-converter CTAs; one occ-2 wave)
    lr_gemm_s1<<<dim3(2, 136), 256, SMEM1_SZ>>>(x, vt, 4096, T, U, ut);

    // Stage 2: out = T @ U^T + bias (K=256): 2048 CTAs, occ 2
    lr_gemm_s2<<<dim3(4096 / 128, 8192 / 128), 256, SMEM2_SZ>>>(
        T, ut, 256, 4096, bias, out);
}